// round 1
// baseline (speedup 1.0000x reference)
#include <cuda_runtime.h>
#include <cuda_bf16.h>

#define N_NODES 50000
#define E_EDGES 800000
#define H_DIM   64
#define GAMMA   0.2f

// ---------------- device scratch (static, allocation-free) ----------------
__device__ float    g_vsrc[H_DIM];
__device__ float    g_vdst[H_DIM];
__device__ float    g_s[N_NODES];
__device__ float    g_d[N_NODES];
__device__ unsigned g_menc[N_NODES];
__device__ float    g_denom[N_NODES];
__device__ float    g_e[E_EDGES];
__device__ float    g_h[N_NODES * H_DIM];
__device__ float    g_crf[N_NODES * H_DIM];
__device__ float    g_sumA;
__device__ float    g_sumB;

// order-preserving float<->uint encoding for atomicMax on signed floats
__device__ __forceinline__ unsigned fenc(float f) {
    unsigned b = __float_as_uint(f);
    return (b & 0x80000000u) ? ~b : (b | 0x80000000u);
}
__device__ __forceinline__ float fdec(unsigned e) {
    return __uint_as_float((e & 0x80000000u) ? (e ^ 0x80000000u) : ~e);
}

// ---------------- kernels ----------------

// v_src = W^T a_src, v_dst = W^T a_dst ; zero loss accumulators
__global__ void k_prep(const float* __restrict__ W, const float* __restrict__ attn) {
    int t = threadIdx.x;  // 128 threads
    if (t == 0) { g_sumA = 0.f; g_sumB = 0.f; }
    if (t < H_DIM) {
        float acc = 0.f;
        #pragma unroll 8
        for (int r = 0; r < H_DIM; r++) acc += attn[r] * W[r * H_DIM + t];
        g_vsrc[t] = acc;
    } else {
        int c = t - H_DIM;
        float acc = 0.f;
        #pragma unroll 8
        for (int r = 0; r < H_DIM; r++) acc += attn[H_DIM + r] * W[r * H_DIM + c];
        g_vdst[c] = acc;
    }
}

// per node: s = h.v_src, d = h.v_dst ; init menc/denom ; zero crf row
// 8 threads per node, each handles 8 floats
__global__ void k_node_scores(const float* __restrict__ h) {
    int gid  = blockIdx.x * blockDim.x + threadIdx.x;
    int node = gid >> 3;
    int part = gid & 7;
    if (node >= N_NODES) return;   // partial exits are whole-warp aligned here

    const float4* hp = (const float4*)(h + (size_t)node * H_DIM);
    const float4* vs = (const float4*)g_vsrc;
    const float4* vd = (const float4*)g_vdst;
    float4 a = hp[part * 2], b = hp[part * 2 + 1];
    float4 v0 = vs[part * 2], v1 = vs[part * 2 + 1];
    float4 w0 = vd[part * 2], w1 = vd[part * 2 + 1];

    float s = a.x * v0.x + a.y * v0.y + a.z * v0.z + a.w * v0.w
            + b.x * v1.x + b.y * v1.y + b.z * v1.z + b.w * v1.w;
    float d = a.x * w0.x + a.y * w0.y + a.z * w0.z + a.w * w0.w
            + b.x * w1.x + b.y * w1.y + b.z * w1.z + b.w * w1.w;

    #pragma unroll
    for (int off = 4; off; off >>= 1) {
        s += __shfl_xor_sync(0xffffffffu, s, off);
        d += __shfl_xor_sync(0xffffffffu, d, off);
    }
    if (part == 0) {
        g_s[node]     = s;
        g_d[node]     = d;
        g_menc[node]  = 0u;     // below every real encoding
        g_denom[node] = 0.f;
    }
    float4* cp = (float4*)(g_crf + (size_t)node * H_DIM);
    cp[part * 2]     = make_float4(0.f, 0.f, 0.f, 0.f);
    cp[part * 2 + 1] = make_float4(0.f, 0.f, 0.f, 0.f);
}

// per edge: e = leaky(s[src]+d[dst]); segment max via encoded atomicMax
__global__ void k_edge_e(const int* __restrict__ src, const int* __restrict__ dst) {
    int i = blockIdx.x * blockDim.x + threadIdx.x;
    if (i >= E_EDGES) return;
    int d0 = dst[i];
    float e = g_s[src[i]] + g_d[d0];
    e = e > 0.f ? e : GAMMA * e;
    g_e[i] = e;
    atomicMax(&g_menc[d0], fenc(e));
}

// per edge (16 threads): ex = exp(e - m[dst]); denom[dst]+=ex; crf[dst]+=ex*h[src]
__global__ void k_edge_acc(const int* __restrict__ src, const int* __restrict__ dst,
                           const float* __restrict__ h) {
    int gid  = blockIdx.x * blockDim.x + threadIdx.x;
    int e    = gid >> 4;
    int part = gid & 15;
    if (e >= E_EDGES) return;
    int s0 = src[e], d0 = dst[e];
    float ex = __expf(g_e[e] - fdec(g_menc[d0]));
    if (part == 0) atomicAdd(&g_denom[d0], ex);
    float4 hv = *(const float4*)(h + (size_t)s0 * H_DIM + part * 4);
    float4 c  = make_float4(ex * hv.x, ex * hv.y, ex * hv.z, ex * hv.w);
    atomicAdd((float4*)(g_crf + (size_t)d0 * H_DIM + part * 4), c);
}

// per node (16 threads): h_new = 0.5*(emb + crf/denom); FINAL: accumulate ||h-emb||^2
template <int FINAL>
__global__ void k_node_update(const float* __restrict__ emb, float* __restrict__ hout) {
    int gid  = blockIdx.x * blockDim.x + threadIdx.x;   // exact grid: N*16
    int node = gid >> 4;
    int part = gid & 15;
    float inv = 1.f / fmaxf(g_denom[node], 1e-16f);
    float4 eb = *(const float4*)(emb + (size_t)node * H_DIM + part * 4);
    float4 cf = *(const float4*)(g_crf + (size_t)node * H_DIM + part * 4);
    float4 hv = make_float4(0.5f * (eb.x + cf.x * inv), 0.5f * (eb.y + cf.y * inv),
                            0.5f * (eb.z + cf.z * inv), 0.5f * (eb.w + cf.w * inv));
    *(float4*)(hout + (size_t)node * H_DIM + part * 4) = hv;

    if (FINAL) {
        float dx = hv.x - eb.x, dy = hv.y - eb.y, dz = hv.z - eb.z, dw = hv.w - eb.w;
        float sq = dx * dx + dy * dy + dz * dz + dw * dw;
        #pragma unroll
        for (int off = 16; off; off >>= 1) sq += __shfl_xor_sync(0xffffffffu, sq, off);
        __shared__ float sm[8];
        if ((threadIdx.x & 31) == 0) sm[threadIdx.x >> 5] = sq;
        __syncthreads();
        if (threadIdx.x < 8) {
            float v = sm[threadIdx.x];
            #pragma unroll
            for (int o = 4; o; o >>= 1) v += __shfl_xor_sync(0xffu, v, o);
            if (threadIdx.x == 0) atomicAdd(&g_sumA, v);
        }
    }
}

// per edge (16 threads): sumB += att * ||h[dst]-h[src]||
__global__ void k_edge_loss(const int* __restrict__ src, const int* __restrict__ dst,
                            const float* __restrict__ h) {
    int gid  = blockIdx.x * blockDim.x + threadIdx.x;   // exact grid: E*16
    int e    = gid >> 4;
    int part = gid & 15;
    int s0 = src[e], d0 = dst[e];
    float4 a = *(const float4*)(h + (size_t)s0 * H_DIM + part * 4);
    float4 b = *(const float4*)(h + (size_t)d0 * H_DIM + part * 4);
    float dx = b.x - a.x, dy = b.y - a.y, dz = b.z - a.z, dw = b.w - a.w;
    float sq = dx * dx + dy * dy + dz * dz + dw * dw;
    #pragma unroll
    for (int off = 8; off; off >>= 1) sq += __shfl_xor_sync(0xffffffffu, sq, off);

    float val = 0.f;
    if (part == 0) {
        float att = __expf(g_e[e] - fdec(g_menc[d0])) / fmaxf(g_denom[d0], 1e-16f);
        val = att * sqrtf(sq + 1e-12f);
    }
    #pragma unroll
    for (int off = 16; off; off >>= 1) val += __shfl_xor_sync(0xffffffffu, val, off);
    __shared__ float sm[8];
    if ((threadIdx.x & 31) == 0) sm[threadIdx.x >> 5] = val;
    __syncthreads();
    if (threadIdx.x < 8) {
        float v = sm[threadIdx.x];
        #pragma unroll
        for (int o = 4; o; o >>= 1) v += __shfl_xor_sync(0xffu, v, o);
        if (threadIdx.x == 0) atomicAdd(&g_sumB, v);
    }
}

__global__ void k_finalize(float* __restrict__ out) {
    out[N_NODES * H_DIM] = 0.5f * (g_sumA + g_sumB) / (float)N_NODES;
}

// ---------------- launch ----------------
extern "C" void kernel_launch(void* const* d_in, const int* in_sizes, int n_in,
                              void* d_out, int out_size) {
    const float* emb  = (const float*)d_in[0];   // [N, H]
    const float* W    = (const float*)d_in[1];   // [H, H]
    const float* attn = (const float*)d_in[2];   // [1, 2H]
    const int*   src  = (const int*)d_in[3];     // [E]
    const int*   dst  = (const int*)d_in[4];     // [E]
    float* out = (float*)d_out;                  // [N*H + 1]

    float* h_buf = nullptr;
    cudaGetSymbolAddress((void**)&h_buf, g_h);

    const int NB_SCORE  = (N_NODES * 8 + 255) / 256;   // 1563
    const int NB_EDGE1  = (E_EDGES + 255) / 256;       // 3125
    const int NB_EDGE16 = (E_EDGES * 16) / 256;        // 50000 (exact)
    const int NB_NODE16 = (N_NODES * 16) / 256;        // 3125  (exact)

    k_prep<<<1, 128>>>(W, attn);

    // ---- layer 0 (input: emb, output: g_h) ----
    k_node_scores<<<NB_SCORE, 256>>>(emb);
    k_edge_e<<<NB_EDGE1, 256>>>(src, dst);
    k_edge_acc<<<NB_EDGE16, 256>>>(src, dst, emb);
    k_node_update<0><<<NB_NODE16, 256>>>(emb, h_buf);

    // ---- layer 1 (input: g_h, output: d_out as h) ----
    k_node_scores<<<NB_SCORE, 256>>>(h_buf);
    k_edge_e<<<NB_EDGE1, 256>>>(src, dst);
    k_edge_acc<<<NB_EDGE16, 256>>>(src, dst, h_buf);
    k_node_update<1><<<NB_NODE16, 256>>>(emb, out);

    // ---- loss ----
    k_edge_loss<<<NB_EDGE16, 256>>>(src, dst, out);
    k_finalize<<<1, 1>>>(out);
}

// round 3
// speedup vs baseline: 1.3949x; 1.3949x over previous
#include <cuda_runtime.h>
#include <cuda_bf16.h>

#define N_NODES 50000
#define E_EDGES 800000
#define H_DIM   64
#define GAMMA   0.2f

// ---------------- device scratch (static, allocation-free) ----------------
__device__ float    g_vsrc[H_DIM];
__device__ float    g_vdst[H_DIM];
__device__ float    g_s[N_NODES];
__device__ float    g_d[N_NODES];
__device__ unsigned g_cnt[N_NODES];
__device__ unsigned g_rowptr[N_NODES + 1];
__device__ unsigned g_cursor[N_NODES];
__device__ int      g_srcs[E_EDGES];      // src id, grouped by dst (CSR)
__device__ float    g_ex[E_EDGES];        // last-layer exp(e-m), CSR order
__device__ float    g_dinv[N_NODES];      // last-layer 1/denom
__device__ float    g_h[N_NODES * H_DIM];
__device__ float    g_sumA;
__device__ float    g_sumB;

// ---------------- kernels ----------------

// v_src = W^T a_src, v_dst = W^T a_dst ; zero loss accumulators
__global__ void k_prep(const float* __restrict__ W, const float* __restrict__ attn) {
    int t = threadIdx.x;  // 128 threads
    if (t == 0) { g_sumA = 0.f; g_sumB = 0.f; }
    if (t < H_DIM) {
        float acc = 0.f;
        #pragma unroll 8
        for (int r = 0; r < H_DIM; r++) acc += attn[r] * W[r * H_DIM + t];
        g_vsrc[t] = acc;
    } else {
        int c = t - H_DIM;
        float acc = 0.f;
        #pragma unroll 8
        for (int r = 0; r < H_DIM; r++) acc += attn[H_DIM + r] * W[r * H_DIM + c];
        g_vdst[c] = acc;
    }
}

__global__ void k_zero_cnt() {
    int i = blockIdx.x * blockDim.x + threadIdx.x;
    if (i < N_NODES) g_cnt[i] = 0u;
}

__global__ void k_hist(const int* __restrict__ dst) {
    int i = blockIdx.x * blockDim.x + threadIdx.x;
    if (i < E_EDGES) atomicAdd(&g_cnt[dst[i]], 1u);
}

// single-block exclusive scan of g_cnt -> g_rowptr / g_cursor
__global__ void k_scan() {
    __shared__ unsigned warp_sums[32];
    int t = threadIdx.x, lane = t & 31, wid = t >> 5;
    unsigned running = 0;
    for (int base = 0; base < N_NODES; base += 1024) {
        int idx = base + t;
        unsigned orig = (idx < N_NODES) ? g_cnt[idx] : 0u;
        unsigned v = orig;
        #pragma unroll
        for (int o = 1; o < 32; o <<= 1) {
            unsigned u = __shfl_up_sync(0xffffffffu, v, o);
            if (lane >= o) v += u;
        }
        if (lane == 31) warp_sums[wid] = v;
        __syncthreads();
        if (wid == 0) {
            unsigned w = warp_sums[lane];
            #pragma unroll
            for (int o = 1; o < 32; o <<= 1) {
                unsigned u = __shfl_up_sync(0xffffffffu, w, o);
                if (lane >= o) w += u;
            }
            warp_sums[lane] = w;
        }
        __syncthreads();
        unsigned pre = (wid > 0) ? warp_sums[wid - 1] : 0u;
        unsigned excl = running + pre + v - orig;
        if (idx < N_NODES) { g_rowptr[idx] = excl; g_cursor[idx] = excl; }
        running += warp_sums[31];
        __syncthreads();
    }
    if (t == 0) g_rowptr[N_NODES] = running;
}

__global__ void k_scatter(const int* __restrict__ src, const int* __restrict__ dst) {
    int i = blockIdx.x * blockDim.x + threadIdx.x;
    if (i >= E_EDGES) return;
    unsigned pos = atomicAdd(&g_cursor[dst[i]], 1u);
    g_srcs[pos] = src[i];
}

// per node: s = h.v_src, d = h.v_dst  (8 threads per node)
__global__ void k_node_scores(const float* __restrict__ h) {
    int gid  = blockIdx.x * blockDim.x + threadIdx.x;
    int node = gid >> 3;
    int part = gid & 7;
    if (node >= N_NODES) return;   // whole-warp aligned exits (N*8 % 32 == 0)

    const float4* hp = (const float4*)(h + (size_t)node * H_DIM);
    const float4* vs = (const float4*)g_vsrc;
    const float4* vd = (const float4*)g_vdst;
    float4 a = hp[part * 2], b = hp[part * 2 + 1];
    float4 v0 = vs[part * 2], v1 = vs[part * 2 + 1];
    float4 w0 = vd[part * 2], w1 = vd[part * 2 + 1];

    float s = a.x * v0.x + a.y * v0.y + a.z * v0.z + a.w * v0.w
            + b.x * v1.x + b.y * v1.y + b.z * v1.z + b.w * v1.w;
    float d = a.x * w0.x + a.y * w0.y + a.z * w0.z + a.w * w0.w
            + b.x * w1.x + b.y * w1.y + b.z * w1.z + b.w * w1.w;

    #pragma unroll
    for (int off = 4; off; off >>= 1) {
        s += __shfl_xor_sync(0xffffffffu, s, off);
        d += __shfl_xor_sync(0xffffffffu, d, off);
    }
    if (part == 0) { g_s[node] = s; g_d[node] = d; }
}

// fused per-node layer: segment max + softmax-weighted gather + node update.
// 16 threads per node; no atomics in the hot path.
template <int FINAL>
__global__ void k_layer(const float* __restrict__ h_in,
                        const float* __restrict__ emb,
                        float* __restrict__ h_out) {
    int gid  = blockIdx.x * blockDim.x + threadIdx.x;   // exact grid: N*16
    int node = gid >> 4;
    int part = gid & 15;
    unsigned gmask = 0xFFFFu << (threadIdx.x & 16);     // this 16-lane group

    unsigned beg = g_rowptr[node], end = g_rowptr[node + 1];
    float dloc = g_d[node];

    // pass 1: segment max (lanes split edges; no syncs inside the loop)
    float m = -3.0e38f;
    for (unsigned j = beg + part; j < end; j += 16) {
        float e = g_s[g_srcs[j]] + dloc;
        e = e > 0.f ? e : GAMMA * e;
        m = fmaxf(m, e);
    }
    #pragma unroll
    for (int off = 8; off; off >>= 1)
        m = fmaxf(m, __shfl_xor_sync(gmask, m, off));

    // pass 2: accumulate; den computed redundantly per lane (no reduction needed)
    float4 acc = make_float4(0.f, 0.f, 0.f, 0.f);
    float den = 0.f;
    for (unsigned j = beg; j < end; j++) {
        int sj = g_srcs[j];                    // uniform within group -> broadcast
        float e = g_s[sj] + dloc;              // L1-resident scalar
        e = e > 0.f ? e : GAMMA * e;
        float ex = __expf(e - m);
        den += ex;
        float4 hv = *(const float4*)(h_in + (size_t)sj * H_DIM + part * 4);
        acc.x += ex * hv.x; acc.y += ex * hv.y;
        acc.z += ex * hv.z; acc.w += ex * hv.w;
        if (FINAL && part == 0) g_ex[j] = ex;
    }
    float inv = 1.f / fmaxf(den, 1e-16f);
    float4 eb = *(const float4*)(emb + (size_t)node * H_DIM + part * 4);
    float4 hv = make_float4(0.5f * (eb.x + acc.x * inv), 0.5f * (eb.y + acc.y * inv),
                            0.5f * (eb.z + acc.z * inv), 0.5f * (eb.w + acc.w * inv));
    *(float4*)(h_out + (size_t)node * H_DIM + part * 4) = hv;

    if (FINAL) {
        if (part == 0) g_dinv[node] = inv;
        float dx = hv.x - eb.x, dy = hv.y - eb.y, dz = hv.z - eb.z, dw = hv.w - eb.w;
        float sq = dx * dx + dy * dy + dz * dz + dw * dw;
        // all lanes converged here: full-warp reduction is safe
        #pragma unroll
        for (int off = 16; off; off >>= 1) sq += __shfl_xor_sync(0xffffffffu, sq, off);
        __shared__ float sm[8];
        if ((threadIdx.x & 31) == 0) sm[threadIdx.x >> 5] = sq;
        __syncthreads();
        if (threadIdx.x < 8) {
            float v = sm[threadIdx.x];
            #pragma unroll
            for (int o = 4; o; o >>= 1) v += __shfl_xor_sync(0xffu, v, o);
            if (threadIdx.x == 0) atomicAdd(&g_sumA, v);
        }
    }
}

// node-parallel loss_b: sumB += sum_edges att * ||h[dst]-h[src]||
// CRITICAL: in-loop shuffles use the 16-lane GROUP mask (groups in one warp
// have different trip counts; a full-mask sync inside the loop deadlocks).
__global__ void k_loss(const float* __restrict__ h) {
    int gid  = blockIdx.x * blockDim.x + threadIdx.x;   // exact grid: N*16
    int node = gid >> 4;
    int part = gid & 15;
    unsigned gmask = 0xFFFFu << (threadIdx.x & 16);

    unsigned beg = g_rowptr[node], end = g_rowptr[node + 1];
    float4 hd = *(const float4*)(h + (size_t)node * H_DIM + part * 4);
    float dinv = g_dinv[node];

    float sum = 0.f;
    for (unsigned j = beg; j < end; j++) {
        int sj = g_srcs[j];
        float4 hs = *(const float4*)(h + (size_t)sj * H_DIM + part * 4);
        float dx = hd.x - hs.x, dy = hd.y - hs.y, dz = hd.z - hs.z, dw = hd.w - hs.w;
        float sq = dx * dx + dy * dy + dz * dz + dw * dw;
        #pragma unroll
        for (int off = 8; off; off >>= 1)
            sq += __shfl_xor_sync(gmask, sq, off);      // group-local, legal under divergence
        sum += g_ex[j] * dinv * sqrtf(sq + 1e-12f);
    }
    if (part != 0) sum = 0.f;   // keep one copy per node
    // converged below loop: full-warp reduction safe
    #pragma unroll
    for (int off = 16; off; off >>= 1) sum += __shfl_xor_sync(0xffffffffu, sum, off);
    __shared__ float sm[8];
    if ((threadIdx.x & 31) == 0) sm[threadIdx.x >> 5] = sum;
    __syncthreads();
    if (threadIdx.x < 8) {
        float v = sm[threadIdx.x];
        #pragma unroll
        for (int o = 4; o; o >>= 1) v += __shfl_xor_sync(0xffu, v, o);
        if (threadIdx.x == 0) atomicAdd(&g_sumB, v);
    }
}

__global__ void k_finalize(float* __restrict__ out) {
    out[N_NODES * H_DIM] = 0.5f * (g_sumA + g_sumB) / (float)N_NODES;
}

// ---------------- launch ----------------
extern "C" void kernel_launch(void* const* d_in, const int* in_sizes, int n_in,
                              void* d_out, int out_size) {
    const float* emb  = (const float*)d_in[0];   // [N, H]
    const float* W    = (const float*)d_in[1];   // [H, H]
    const float* attn = (const float*)d_in[2];   // [1, 2H]
    const int*   src  = (const int*)d_in[3];     // [E]
    const int*   dst  = (const int*)d_in[4];     // [E]
    float* out = (float*)d_out;                  // [N*H + 1]

    float* h_buf = nullptr;
    cudaGetSymbolAddress((void**)&h_buf, g_h);

    const int NB_NODE1  = (N_NODES + 255) / 256;       // 196
    const int NB_EDGE1  = (E_EDGES + 255) / 256;       // 3125
    const int NB_SCORE  = (N_NODES * 8 + 255) / 256;   // 1563
    const int NB_NODE16 = (N_NODES * 16) / 256;        // 3125 (exact)

    k_prep<<<1, 128>>>(W, attn);

    // ---- CSR build (dst-grouped) ----
    k_zero_cnt<<<NB_NODE1, 256>>>();
    k_hist<<<NB_EDGE1, 256>>>(dst);
    k_scan<<<1, 1024>>>();
    k_scatter<<<NB_EDGE1, 256>>>(src, dst);

    // ---- layer 0 (input: emb, output: g_h) ----
    k_node_scores<<<NB_SCORE, 256>>>(emb);
    k_layer<0><<<NB_NODE16, 256>>>(emb, emb, h_buf);

    // ---- layer 1 (input: g_h, output: d_out as h) ----
    k_node_scores<<<NB_SCORE, 256>>>(h_buf);
    k_layer<1><<<NB_NODE16, 256>>>(h_buf, emb, out);

    // ---- loss ----
    k_loss<<<NB_NODE16, 256>>>(out);
    k_finalize<<<1, 1>>>(out);
}

// round 4
// speedup vs baseline: 1.6020x; 1.1485x over previous
#include <cuda_runtime.h>
#include <cuda_bf16.h>

#define N_NODES 50000
#define E_EDGES 800000
#define H_DIM   64
#define GAMMA   0.2f

#define SCAN_CHUNK 1024
#define SCAN_NBLK  ((N_NODES + SCAN_CHUNK - 1) / SCAN_CHUNK)   // 49

// ---------------- device scratch (static, allocation-free) ----------------
__device__ float    g_vsrc[H_DIM];
__device__ float    g_vdst[H_DIM];
__device__ float    g_s[N_NODES];
__device__ float    g_d[N_NODES];
__device__ unsigned g_cnt[N_NODES];
__device__ unsigned g_rowptr[N_NODES + 1];
__device__ unsigned g_cursor[N_NODES];
__device__ unsigned g_blksum[SCAN_NBLK];
__device__ unsigned g_blkoff[SCAN_NBLK];
__device__ int      g_srcs[E_EDGES];      // src id, grouped by dst (CSR)
__device__ float    g_ex[E_EDGES];        // last-layer exp(e-m), CSR order
__device__ float    g_dinv[N_NODES];      // last-layer 1/denom
__device__ float    g_h[N_NODES * H_DIM];
__device__ float    g_sumA;
__device__ float    g_sumB;

// ---------------- kernels ----------------

// v_src = W^T a_src, v_dst = W^T a_dst ; zero loss accumulators
__global__ void k_prep(const float* __restrict__ W, const float* __restrict__ attn) {
    int t = threadIdx.x;  // 128 threads
    if (t == 0) { g_sumA = 0.f; g_sumB = 0.f; }
    if (t < H_DIM) {
        float acc = 0.f;
        #pragma unroll 8
        for (int r = 0; r < H_DIM; r++) acc += attn[r] * W[r * H_DIM + t];
        g_vsrc[t] = acc;
    } else {
        int c = t - H_DIM;
        float acc = 0.f;
        #pragma unroll 8
        for (int r = 0; r < H_DIM; r++) acc += attn[H_DIM + r] * W[r * H_DIM + c];
        g_vdst[c] = acc;
    }
}

__global__ void k_zero_cnt() {
    int i = blockIdx.x * blockDim.x + threadIdx.x;
    if (i < N_NODES) g_cnt[i] = 0u;
}

__global__ void k_hist(const int* __restrict__ dst) {
    int i = blockIdx.x * blockDim.x + threadIdx.x;
    if (i < E_EDGES) atomicAdd(&g_cnt[dst[i]], 1u);
}

// step 1: per-block exclusive scan of g_cnt -> g_rowptr (block-local), totals -> g_blksum
__global__ void k_scan1() {
    __shared__ unsigned warp_sums[32];
    int t = threadIdx.x, lane = t & 31, wid = t >> 5;
    int idx = blockIdx.x * SCAN_CHUNK + t;

    unsigned orig = (idx < N_NODES) ? g_cnt[idx] : 0u;
    unsigned v = orig;
    #pragma unroll
    for (int o = 1; o < 32; o <<= 1) {
        unsigned u = __shfl_up_sync(0xffffffffu, v, o);
        if (lane >= o) v += u;
    }
    if (lane == 31) warp_sums[wid] = v;
    __syncthreads();
    if (wid == 0) {
        unsigned w = warp_sums[lane];
        #pragma unroll
        for (int o = 1; o < 32; o <<= 1) {
            unsigned u = __shfl_up_sync(0xffffffffu, w, o);
            if (lane >= o) w += u;
        }
        warp_sums[lane] = w;
    }
    __syncthreads();
    unsigned pre = (wid > 0) ? warp_sums[wid - 1] : 0u;
    if (idx < N_NODES) g_rowptr[idx] = pre + v - orig;   // block-local exclusive
    if (t == SCAN_CHUNK - 1) g_blksum[blockIdx.x] = warp_sums[31];
}

// step 2: one warp scans SCAN_NBLK (=49) block totals -> g_blkoff (exclusive), total -> rowptr[N]
__global__ void k_scan2() {
    int lane = threadIdx.x;  // 32 threads
    unsigned o0 = (lane < SCAN_NBLK) ? g_blksum[lane] : 0u;
    unsigned o1 = (32 + lane < SCAN_NBLK) ? g_blksum[32 + lane] : 0u;
    unsigned v0 = o0, v1 = o1;
    #pragma unroll
    for (int o = 1; o < 32; o <<= 1) {
        unsigned u0 = __shfl_up_sync(0xffffffffu, v0, o);
        unsigned u1 = __shfl_up_sync(0xffffffffu, v1, o);
        if (lane >= o) { v0 += u0; v1 += u1; }
    }
    unsigned tot0 = __shfl_sync(0xffffffffu, v0, 31);
    v1 += tot0;
    unsigned total = __shfl_sync(0xffffffffu, v1, 31);
    if (lane < SCAN_NBLK) g_blkoff[lane] = v0 - o0;
    if (32 + lane < SCAN_NBLK) g_blkoff[32 + lane] = v1 - o1;
    if (lane == 0) g_rowptr[N_NODES] = total;
}

// step 3: add block offsets; mirror into g_cursor
__global__ void k_scan3() {
    int i = blockIdx.x * blockDim.x + threadIdx.x;
    if (i >= N_NODES) return;
    unsigned r = g_rowptr[i] + g_blkoff[i / SCAN_CHUNK];
    g_rowptr[i] = r;
    g_cursor[i] = r;
}

__global__ void k_scatter(const int* __restrict__ src, const int* __restrict__ dst) {
    int i = blockIdx.x * blockDim.x + threadIdx.x;
    if (i >= E_EDGES) return;
    unsigned pos = atomicAdd(&g_cursor[dst[i]], 1u);
    g_srcs[pos] = src[i];
}

// per node: s = h.v_src, d = h.v_dst  (8 threads per node)
__global__ void k_node_scores(const float* __restrict__ h) {
    int gid  = blockIdx.x * blockDim.x + threadIdx.x;
    int node = gid >> 3;
    int part = gid & 7;
    if (node >= N_NODES) return;   // whole-warp aligned exits (N*8 % 32 == 0)

    const float4* hp = (const float4*)(h + (size_t)node * H_DIM);
    const float4* vs = (const float4*)g_vsrc;
    const float4* vd = (const float4*)g_vdst;
    float4 a = hp[part * 2], b = hp[part * 2 + 1];
    float4 v0 = vs[part * 2], v1 = vs[part * 2 + 1];
    float4 w0 = vd[part * 2], w1 = vd[part * 2 + 1];

    float s = a.x * v0.x + a.y * v0.y + a.z * v0.z + a.w * v0.w
            + b.x * v1.x + b.y * v1.y + b.z * v1.z + b.w * v1.w;
    float d = a.x * w0.x + a.y * w0.y + a.z * w0.z + a.w * w0.w
            + b.x * w1.x + b.y * w1.y + b.z * w1.z + b.w * w1.w;

    #pragma unroll
    for (int off = 4; off; off >>= 1) {
        s += __shfl_xor_sync(0xffffffffu, s, off);
        d += __shfl_xor_sync(0xffffffffu, d, off);
    }
    if (part == 0) { g_s[node] = s; g_d[node] = d; }
}

// fused per-node layer: segment max + softmax-weighted gather + node update.
// 16 threads per node; no atomics in the hot path.
template <int FINAL>
__global__ void k_layer(const float* __restrict__ h_in,
                        const float* __restrict__ emb,
                        float* __restrict__ h_out) {
    int gid  = blockIdx.x * blockDim.x + threadIdx.x;   // exact grid: N*16
    int node = gid >> 4;
    int part = gid & 15;
    unsigned gmask = 0xFFFFu << (threadIdx.x & 16);     // this 16-lane group

    unsigned beg = g_rowptr[node], end = g_rowptr[node + 1];
    float dloc = g_d[node];

    // pass 1: segment max (lanes split edges; no syncs inside the loop)
    float m = -3.0e38f;
    for (unsigned j = beg + part; j < end; j += 16) {
        float e = g_s[g_srcs[j]] + dloc;
        e = e > 0.f ? e : GAMMA * e;
        m = fmaxf(m, e);
    }
    #pragma unroll
    for (int off = 8; off; off >>= 1)
        m = fmaxf(m, __shfl_xor_sync(gmask, m, off));

    // pass 2: accumulate; den computed redundantly per lane (no reduction needed)
    float4 acc = make_float4(0.f, 0.f, 0.f, 0.f);
    float den = 0.f;
    for (unsigned j = beg; j < end; j++) {
        int sj = g_srcs[j];                    // uniform within group -> broadcast
        float e = g_s[sj] + dloc;              // L1-resident scalar
        e = e > 0.f ? e : GAMMA * e;
        float ex = __expf(e - m);
        den += ex;
        float4 hv = *(const float4*)(h_in + (size_t)sj * H_DIM + part * 4);
        acc.x += ex * hv.x; acc.y += ex * hv.y;
        acc.z += ex * hv.z; acc.w += ex * hv.w;
        if (FINAL && part == 0) g_ex[j] = ex;
    }
    float inv = 1.f / fmaxf(den, 1e-16f);
    float4 eb = *(const float4*)(emb + (size_t)node * H_DIM + part * 4);
    float4 hv = make_float4(0.5f * (eb.x + acc.x * inv), 0.5f * (eb.y + acc.y * inv),
                            0.5f * (eb.z + acc.z * inv), 0.5f * (eb.w + acc.w * inv));
    *(float4*)(h_out + (size_t)node * H_DIM + part * 4) = hv;

    if (FINAL) {
        if (part == 0) g_dinv[node] = inv;
        float dx = hv.x - eb.x, dy = hv.y - eb.y, dz = hv.z - eb.z, dw = hv.w - eb.w;
        float sq = dx * dx + dy * dy + dz * dz + dw * dw;
        // all lanes converged here: full-warp reduction is safe
        #pragma unroll
        for (int off = 16; off; off >>= 1) sq += __shfl_xor_sync(0xffffffffu, sq, off);
        __shared__ float sm[8];
        if ((threadIdx.x & 31) == 0) sm[threadIdx.x >> 5] = sq;
        __syncthreads();
        if (threadIdx.x < 8) {
            float v = sm[threadIdx.x];
            #pragma unroll
            for (int o = 4; o; o >>= 1) v += __shfl_xor_sync(0xffu, v, o);
            if (threadIdx.x == 0) atomicAdd(&g_sumA, v);
        }
    }
}

// node-parallel loss_b: sumB += sum_edges att * ||h[dst]-h[src]||
// In-loop shuffles use the 16-lane GROUP mask (groups in one warp have
// different trip counts; full-mask sync inside the loop would deadlock).
__global__ void k_loss(const float* __restrict__ h) {
    int gid  = blockIdx.x * blockDim.x + threadIdx.x;   // exact grid: N*16
    int node = gid >> 4;
    int part = gid & 15;
    unsigned gmask = 0xFFFFu << (threadIdx.x & 16);

    unsigned beg = g_rowptr[node], end = g_rowptr[node + 1];
    float4 hd = *(const float4*)(h + (size_t)node * H_DIM + part * 4);
    float dinv = g_dinv[node];

    float sum = 0.f;
    for (unsigned j = beg; j < end; j++) {
        int sj = g_srcs[j];
        float4 hs = *(const float4*)(h + (size_t)sj * H_DIM + part * 4);
        float dx = hd.x - hs.x, dy = hd.y - hs.y, dz = hd.z - hs.z, dw = hd.w - hs.w;
        float sq = dx * dx + dy * dy + dz * dz + dw * dw;
        #pragma unroll
        for (int off = 8; off; off >>= 1)
            sq += __shfl_xor_sync(gmask, sq, off);      // group-local, legal under divergence
        sum += g_ex[j] * dinv * sqrtf(sq + 1e-12f);
    }
    if (part != 0) sum = 0.f;   // keep one copy per node
    // converged below loop: full-warp reduction safe
    #pragma unroll
    for (int off = 16; off; off >>= 1) sum += __shfl_xor_sync(0xffffffffu, sum, off);
    __shared__ float sm[8];
    if ((threadIdx.x & 31) == 0) sm[threadIdx.x >> 5] = sum;
    __syncthreads();
    if (threadIdx.x < 8) {
        float v = sm[threadIdx.x];
        #pragma unroll
        for (int o = 4; o; o >>= 1) v += __shfl_xor_sync(0xffu, v, o);
        if (threadIdx.x == 0) atomicAdd(&g_sumB, v);
    }
}

__global__ void k_finalize(float* __restrict__ out) {
    out[N_NODES * H_DIM] = 0.5f * (g_sumA + g_sumB) / (float)N_NODES;
}

// ---------------- launch ----------------
extern "C" void kernel_launch(void* const* d_in, const int* in_sizes, int n_in,
                              void* d_out, int out_size) {
    const float* emb  = (const float*)d_in[0];   // [N, H]
    const float* W    = (const float*)d_in[1];   // [H, H]
    const float* attn = (const float*)d_in[2];   // [1, 2H]
    const int*   src  = (const int*)d_in[3];     // [E]
    const int*   dst  = (const int*)d_in[4];     // [E]
    float* out = (float*)d_out;                  // [N*H + 1]

    float* h_buf = nullptr;
    cudaGetSymbolAddress((void**)&h_buf, g_h);

    const int NB_NODE1  = (N_NODES + 255) / 256;       // 196
    const int NB_EDGE1  = (E_EDGES + 255) / 256;       // 3125
    const int NB_SCORE  = (N_NODES * 8 + 255) / 256;   // 1563
    const int NB_NODE16 = (N_NODES * 16) / 256;        // 3125 (exact)

    k_prep<<<1, 128>>>(W, attn);

    // ---- CSR build (dst-grouped), hierarchical scan ----
    k_zero_cnt<<<NB_NODE1, 256>>>();
    k_hist<<<NB_EDGE1, 256>>>(dst);
    k_scan1<<<SCAN_NBLK, SCAN_CHUNK>>>();
    k_scan2<<<1, 32>>>();
    k_scan3<<<NB_NODE1, 256>>>();
    k_scatter<<<NB_EDGE1, 256>>>(src, dst);

    // ---- layer 0 (input: emb, output: g_h) ----
    k_node_scores<<<NB_SCORE, 256>>>(emb);
    k_layer<0><<<NB_NODE16, 256>>>(emb, emb, h_buf);

    // ---- layer 1 (input: g_h, output: d_out as h) ----
    k_node_scores<<<NB_SCORE, 256>>>(h_buf);
    k_layer<1><<<NB_NODE16, 256>>>(h_buf, emb, out);

    // ---- loss ----
    k_loss<<<NB_NODE16, 256>>>(out);
    k_finalize<<<1, 1>>>(out);
}